// round 15
// baseline (speedup 1.0000x reference)
#include <cuda_runtime.h>

#define NNAT 16
#define MAX_TILES 200000

// Per-tile packed accumulator written by k_hist piece blocks:
//   bits [42:64) = piece count
//   bits [0:42)  = sum over pieces of (q[nation]+pb+4.0) in fixed point, scale 2^30
// INVARIANT: zero outside a kernel_launch invocation (k_tiles restores zeros).
__device__ unsigned long long g_tcu[MAX_TILES];
// [0,64): sum tile_pos; [64,128): sum count_t*pte; [128,144): nation totals; [144,146): terrain counts
__device__ float g_acc[160];
__device__ float g_u[64];          // W_tile_top @ policy_w
__device__ float g_v[64];          // W_piece_bot @ policy_w
__device__ float g_terrsc[2];      // (terrain_emb @ W_tile_bot) @ policy_w
__device__ float g_nproj[16 * 64]; // nation_emb @ W_piece_top
__device__ float g_tproj[2 * 64];  // terrain_emb @ W_tile_bot
__device__ float g_c0;             // (tile_fc_b + nation_emb[active]) . w + policy_b
__device__ unsigned int g_done;    // last-block epilogue counter (reset by epilogue)

#define QSCALE 1073741824.0f   // 2^30
#define QOFF   4.0f
#define CNT_SHIFT 42
#define PARAM_BLOCKS 17
#define PPT 8                  // pieces per thread in hist blocks

// Fused: blocks 0..15 fold nproj row n; block 16 folds u/v/tproj/terrsc/c0.
// Blocks >= 17 are piece-histogram blocks (self-compute sq via vtop factorization).
__global__ void k_hist(const int* __restrict__ nation_idxs,
                       const int* __restrict__ piece_tile_idxs,
                       int P,
                       const float* __restrict__ tile_fc_w,
                       const float* __restrict__ tile_fc_b,
                       const float* __restrict__ piece_fc_w,
                       const float* __restrict__ piece_fc_b,
                       const float* __restrict__ tile_policy_w,
                       const float* __restrict__ tile_policy_b,
                       const float* __restrict__ nation_emb,
                       const float* __restrict__ terrain_emb,
                       const int*   __restrict__ active_nation)
{
    __shared__ float w[64];
    int tid = threadIdx.x;
    int b = blockIdx.x;

    if (b < PARAM_BLOCKS) {
        __shared__ float rA[64], rB[64], rD[64];
        if (tid < 64) w[tid] = tile_policy_w[tid];
        __syncthreads();

        if (b < 16) {
            if (tid < 64) {
                float s = 0.f;
                #pragma unroll 16
                for (int k = 0; k < 64; k++)
                    s += nation_emb[b * 64 + k] * piece_fc_w[k * 64 + tid];
                g_nproj[b * 64 + tid] = s;
            }
        } else {
            if (tid < 64) {
                float su = 0.f, sv = 0.f, t0 = 0.f, t1 = 0.f;
                #pragma unroll 16
                for (int c = 0; c < 64; c++) {
                    su += tile_fc_w[tid * 64 + c] * w[c];          // u[j]
                    sv += piece_fc_w[(64 + tid) * 64 + c] * w[c];  // v[j]
                }
                #pragma unroll 16
                for (int k = 0; k < 64; k++) {
                    float tw = tile_fc_w[(64 + k) * 64 + tid];
                    t0 += terrain_emb[k] * tw;                     // tproj[0][j]
                    t1 += terrain_emb[64 + k] * tw;                // tproj[1][j]
                }
                g_u[tid] = su;
                g_v[tid] = sv;
                g_tproj[tid] = t0;
                g_tproj[64 + tid] = t1;

                int an = active_nation[0];
                rA[tid] = t0 * w[tid];
                rB[tid] = t1 * w[tid];
                rD[tid] = (tile_fc_b[tid] + nation_emb[an * 64 + tid]) * w[tid];
            }
            __syncthreads();
            if (tid < 3) {
                const float* r = (tid == 0) ? rA : (tid == 1) ? rB : rD;
                float s = 0.f;
                #pragma unroll 16
                for (int k = 0; k < 64; k++) s += r[k];
                if (tid == 0) g_terrsc[0] = s;
                else if (tid == 1) g_terrsc[1] = s;
                else g_c0 = s + tile_policy_b[0];
            }
        }
        return;
    }

    // ---- piece-histogram blocks (PPT pieces per thread) ----
    __shared__ float vtop[64], rP[64];
    __shared__ unsigned long long sq[NNAT];
    __shared__ unsigned int sh[NNAT];

    if (tid < 64) w[tid] = tile_policy_w[tid];
    __syncthreads();

    if (tid < 64) {
        const float4* pr = reinterpret_cast<const float4*>(piece_fc_w + tid * 64);
        float s = 0.f;
        #pragma unroll
        for (int c = 0; c < 16; c++) {
            float4 p = pr[c];
            s += p.x * w[4 * c] + p.y * w[4 * c + 1]
               + p.z * w[4 * c + 2] + p.w * w[4 * c + 3];
        }
        vtop[tid] = s;
    } else if (tid < 128) {
        rP[tid - 64] = piece_fc_b[tid - 64] * w[tid - 64];
    }
    __syncthreads();

    if (tid < NNAT) {
        float pb = 0.f;
        #pragma unroll 16
        for (int j = 0; j < 64; j++) pb += rP[j];
        float q = 0.f;
        #pragma unroll 16
        for (int k = 0; k < 64; k++) q += nation_emb[tid * 64 + k] * vtop[k];
        sq[tid] = (unsigned long long)llroundf((q + pb + QOFF) * QSCALE)
                + (1ULL << CNT_SHIFT);
        sh[tid] = 0u;
    }
    __syncthreads();

    int i = (b - PARAM_BLOCKS) * blockDim.x + tid;
    int Pg = P / PPT;
    if (i < Pg) {
        #pragma unroll
        for (int r = 0; r < PPT / 4; r++) {
            int4 n4 = reinterpret_cast<const int4*>(nation_idxs)[i * (PPT / 4) + r];
            int4 t4 = reinterpret_cast<const int4*>(piece_tile_idxs)[i * (PPT / 4) + r];
            atomicAdd(&g_tcu[t4.x], sq[n4.x]);
            atomicAdd(&g_tcu[t4.y], sq[n4.y]);
            atomicAdd(&g_tcu[t4.z], sq[n4.z]);
            atomicAdd(&g_tcu[t4.w], sq[n4.w]);
            atomicAdd(&sh[n4.x], 1u); atomicAdd(&sh[n4.y], 1u);
            atomicAdd(&sh[n4.z], 1u); atomicAdd(&sh[n4.w], 1u);
        }
    }
    int rem = P - Pg * PPT;
    if (i < rem) {
        int idx = Pg * PPT + i;
        atomicAdd(&g_tcu[piece_tile_idxs[idx]], sq[nation_idxs[idx]]);
        atomicAdd(&sh[nation_idxs[idx]], 1u);
    }
    __syncthreads();
    if (tid < NNAT) atomicAdd(&g_acc[128 + tid], (float)sh[tid]);
}

// Half-warp-per-tile float4 layout: 16 lanes x 4 dims, ONE LDG.128 per tile per
// array, 4-level merged butterfly. U=2 pairs -> 4 tiles per warp-iteration.
// terrain + tile_idxs prefetched at loop top (no exposed dependent load after
// the reduce). Self-cleaning scratch; fused last-block epilogue.
__global__ void __launch_bounds__(256, 4)
k_tiles(const int*   __restrict__ tile_idxs,
        const int*   __restrict__ terrain,
        const float* __restrict__ tile_pos_emb,
        const float* __restrict__ piece_tile_emb,
        float*       __restrict__ out,
        int T, int P,
        const float* __restrict__ tile_fc_w,
        const float* __restrict__ tile_fc_b,
        const float* __restrict__ piece_fc_w,
        const float* __restrict__ piece_fc_b,
        const float* __restrict__ nation_emb,
        const int*   __restrict__ active_nation,
        const float* __restrict__ value_w1,
        const float* __restrict__ value_b1,
        const float* __restrict__ value_w2,
        const float* __restrict__ value_b2,
        const float* __restrict__ end_turn_logit)
{
    const int U = 2;                 // tile-pairs per iteration (4 tiles/warp-iter)
    const int TPW = 2 * U;           // tiles per warp per iteration
    int lane = threadIdx.x & 31;
    int sub  = lane & 15;            // dim group: dims 4*sub..4*sub+3
    int half = lane >> 4;            // which tile of each pair
    int gwid = (blockIdx.x * blockDim.x + threadIdx.x) >> 5;
    int nw   = (gridDim.x * blockDim.x) >> 5;

    float4 u4 = reinterpret_cast<const float4*>(g_u)[sub];
    float4 v4 = reinterpret_cast<const float4*>(g_v)[sub];
    float  c0 = g_c0;
    float  tsc0 = g_terrsc[0], tsc1 = g_terrsc[1];

    float4 ap = make_float4(0.f, 0.f, 0.f, 0.f);  // sum tile_pos (lane's 4 dims)
    float4 ac = make_float4(0.f, 0.f, 0.f, 0.f);  // sum count_t * pte
    float  tcc0 = 0.f, tcc1 = 0.f;                // terrain counts (sub==0 lanes)

    const float4* __restrict__ tp_base = reinterpret_cast<const float4*>(tile_pos_emb);
    const float4* __restrict__ pe_base = reinterpret_cast<const float4*>(piece_tile_emb);

    int nstep = nw * TPW;
    int base = gwid * TPW;

    // Prologue: prefetch first iteration's row indices (broadcast per half).
    int idxc[U];
    #pragma unroll
    for (int i = 0; i < U; i++) {
        int t = base + 2 * i + half;
        idxc[i] = tile_idxs[(t < T) ? t : 0];
    }

    for (; base < T; base += nstep) {
        float4 tp[U], pe[U];
        float  cnt[U], qs[U];
        int    ter[U];
        bool   val[U];

        #pragma unroll
        for (int i = 0; i < U; i++) {
            int t = base + 2 * i + half;
            val[i] = (t < T);
            int tt = val[i] ? t : 0;
            tp[i] = tp_base[idxc[i] * 16 + sub];
            pe[i] = pe_base[tt * 16 + sub];
            unsigned long long pk = val[i] ? g_tcu[tt] : 0ull;  // broadcast 8B
            cnt[i] = (float)(unsigned int)(pk >> CNT_SHIFT);
            qs[i]  = (float)(long long)(pk & ((1ULL << CNT_SHIFT) - 1ull))
                     * (1.0f / QSCALE) - cnt[i] * QOFF;
            ter[i] = terrain[tt];                               // broadcast 4B
        }

        // Prefetch next iteration's row indices while gathers are in flight.
        int nbase = base + nstep;
        #pragma unroll
        for (int i = 0; i < U; i++) {
            int t = nbase + 2 * i + half;
            if (t < T) idxc[i] = tile_idxs[t];
        }

        // Restore zeros for the next graph replay (values already consumed).
        if (sub == 0) {
            #pragma unroll
            for (int i = 0; i < U; i++) {
                int t = base + 2 * i + half;
                if (val[i]) g_tcu[t] = 0ull;
            }
        }

        float s[U];
        #pragma unroll
        for (int i = 0; i < U; i++) {
            if (!val[i]) {
                tp[i] = make_float4(0.f, 0.f, 0.f, 0.f);
                pe[i] = make_float4(0.f, 0.f, 0.f, 0.f);
            }
            s[i] = (tp[i].x * u4.x + tp[i].y * u4.y + tp[i].z * u4.z + tp[i].w * u4.w)
                 + cnt[i] * (pe[i].x * v4.x + pe[i].y * v4.y + pe[i].z * v4.z + pe[i].w * v4.w);
            ap.x += tp[i].x; ap.y += tp[i].y; ap.z += tp[i].z; ap.w += tp[i].w;
            ac.x += cnt[i] * pe[i].x; ac.y += cnt[i] * pe[i].y;
            ac.z += cnt[i] * pe[i].z; ac.w += cnt[i] * pe[i].w;
        }

        // 4-level butterfly within each 16-lane half.
        #pragma unroll
        for (int o = 8; o > 0; o >>= 1) {
            #pragma unroll
            for (int i = 0; i < U; i++)
                s[i] += __shfl_xor_sync(0xffffffffu, s[i], o);
        }

        if (sub == 0) {
            #pragma unroll
            for (int i = 0; i < U; i++) {
                if (val[i]) {
                    int t = base + 2 * i + half;
                    int e = ter[i] - 1;
                    out[t] = s[i] + (e == 0 ? tsc0 : tsc1) + qs[i] + c0;
                    if (e == 0) tcc0 += 1.f; else tcc1 += 1.f;
                }
            }
        }
    }

    atomicAdd(&g_acc[4 * sub + 0],      ap.x);
    atomicAdd(&g_acc[4 * sub + 1],      ap.y);
    atomicAdd(&g_acc[4 * sub + 2],      ap.z);
    atomicAdd(&g_acc[4 * sub + 3],      ap.w);
    atomicAdd(&g_acc[64 + 4 * sub + 0], ac.x);
    atomicAdd(&g_acc[64 + 4 * sub + 1], ac.y);
    atomicAdd(&g_acc[64 + 4 * sub + 2], ac.z);
    atomicAdd(&g_acc[64 + 4 * sub + 3], ac.w);
    if (sub == 0) {
        atomicAdd(&g_acc[144], tcc0);
        atomicAdd(&g_acc[145], tcc1);
    }

    // ---- last-block epilogue (pooled mean -> value MLP) ----
    __threadfence();
    __syncthreads();
    __shared__ bool isLast;
    if (threadIdx.x == 0)
        isLast = (atomicAdd(&g_done, 1u) == gridDim.x - 1);
    __syncthreads();
    if (!isLast) return;

    __shared__ float part[4][64];
    __shared__ float pooled[64];
    __shared__ float h[64];
    int tid = threadIdx.x;
    int c = tid >> 6;       // k-chunk 0..3
    int j = tid & 63;       // output dim
    float fT = (float)T;

    float s = 0.f;
    #pragma unroll 16
    for (int k = c * 16; k < c * 16 + 16; k++) {
        s += g_acc[k]      * tile_fc_w[k * 64 + j];
        s += g_acc[64 + k] * piece_fc_w[(64 + k) * 64 + j];
    }
    #pragma unroll 4
    for (int n = c * 4; n < c * 4 + 4; n++)
        s += g_acc[128 + n] * g_nproj[n * 64 + j];
    if (c == 0) {
        s += g_acc[144] * g_tproj[j] + g_acc[145] * g_tproj[64 + j];
        int an_ = active_nation[0];
        s += fT * tile_fc_b[j] + (float)P * piece_fc_b[j]
           + fT * nation_emb[an_ * 64 + j];
    }
    part[c][j] = s;
    __syncthreads();

    // All g_acc reads are complete: restore zeros for the next replay.
    if (tid < 160) g_acc[tid] = 0.f;
    if (tid == 160) g_done = 0u;

    if (c == 0)
        pooled[j] = (part[0][j] + part[1][j] + part[2][j] + part[3][j]) / fT;
    __syncthreads();

    float hv = 0.f;
    #pragma unroll 16
    for (int k = c * 16; k < c * 16 + 16; k++)
        hv += pooled[k] * value_w1[k * 64 + j];
    part[c][j] = hv;
    __syncthreads();
    if (c == 0) {
        float x = part[0][j] + part[1][j] + part[2][j] + part[3][j] + value_b1[j];
        h[j] = x > 0.f ? x : 0.f;
    }
    __syncthreads();

    if (tid < 32) {
        float v = h[tid] * value_w2[tid] + h[tid + 32] * value_w2[tid + 32];
        #pragma unroll
        for (int o = 16; o > 0; o >>= 1)
            v += __shfl_xor_sync(0xffffffffu, v, o);
        if (tid == 0) {
            out[T]     = end_turn_logit[0];
            out[T + 1] = v + value_b2[0];
        }
    }
}

extern "C" void kernel_launch(void* const* d_in, const int* in_sizes, int n_in,
                              void* d_out, int out_size)
{
    const int*   tile_idxs      = (const int*)  d_in[0];
    const int*   terrain        = (const int*)  d_in[1];
    const int*   nation_idxs    = (const int*)  d_in[2];
    const int*   piece_tidx     = (const int*)  d_in[3];
    const int*   active         = (const int*)  d_in[4];
    const float* tile_pos_emb   = (const float*)d_in[5];
    const float* terrain_emb    = (const float*)d_in[6];
    const float* nation_emb     = (const float*)d_in[7];
    const float* piece_tile_emb = (const float*)d_in[8];
    const float* tile_fc_w      = (const float*)d_in[9];
    const float* tile_fc_b      = (const float*)d_in[10];
    const float* piece_fc_w     = (const float*)d_in[11];
    const float* piece_fc_b     = (const float*)d_in[12];
    const float* tile_policy_w  = (const float*)d_in[13];
    const float* tile_policy_b  = (const float*)d_in[14];
    const float* end_turn       = (const float*)d_in[15];
    const float* value_w1       = (const float*)d_in[16];
    const float* value_b1       = (const float*)d_in[17];
    const float* value_w2       = (const float*)d_in[18];
    const float* value_b2       = (const float*)d_in[19];
    float* out = (float*)d_out;

    int T = in_sizes[0];   // 200000
    int P = in_sizes[2];   // 1000000

    int piece_blocks = (P / PPT + 255) / 256;
    k_hist<<<PARAM_BLOCKS + piece_blocks, 256>>>(
        nation_idxs, piece_tidx, P,
        tile_fc_w, tile_fc_b, piece_fc_w, piece_fc_b,
        tile_policy_w, tile_policy_b, nation_emb, terrain_emb, active);

    k_tiles<<<592, 256>>>(tile_idxs, terrain, tile_pos_emb, piece_tile_emb, out,
                          T, P,
                          tile_fc_w, tile_fc_b, piece_fc_w, piece_fc_b,
                          nation_emb, active,
                          value_w1, value_b1, value_w2, value_b2, end_turn);
}

// round 16
// speedup vs baseline: 2.5171x; 2.5171x over previous
#include <cuda_runtime.h>

#define NNAT 16
#define MAX_TILES 200000

__device__ unsigned long long g_tcu[MAX_TILES];
__device__ float g_acc[160];
__device__ float g_u[64];
__device__ float g_v[64];
__device__ float g_terrsc[2];
__device__ float g_nproj[16 * 64];
__device__ float g_tproj[2 * 64];
__device__ float g_c0;
__device__ unsigned int g_done;

#define QSCALE 1073741824.0f
#define QOFF   4.0f
#define CNT_SHIFT 42
#define PARAM_BLOCKS 17
#define PPT 8

#define CHUNK 40
#define TP_OFF 0
#define PE_OFF 10240
#define TCU_OFF 20480
#define IDX_OFF 20800
#define TER_OFF 20960
#define RES_OFF 21120
#define BUFSTRIDE 21280
#define NBLK 148

__device__ __forceinline__ unsigned smaddr(const void* p) {
    unsigned r;
    asm("{ .reg .u64 t; cvta.to.shared.u64 t, %1; cvt.u32.u64 %0, t; }"
        : "=r"(r) : "l"(p));
    return r;
}

#define BULK_G2S(dst, src, bytes, mbar) \
    asm volatile("cp.async.bulk.shared::cta.global.mbarrier::complete_tx::bytes [%0], [%1], %2, [%3];" \
                 :: "r"(dst), "l"(src), "r"(bytes), "r"(mbar) : "memory")

#define MBAR_INIT(addr, cnt) \
    asm volatile("mbarrier.init.shared.b64 [%0], %1;" :: "r"(addr), "r"(cnt) : "memory")

#define MBAR_EXPECT_TX(addr, bytes) \
    asm volatile("mbarrier.arrive.expect_tx.shared.b64 _, [%0], %1;" :: "r"(addr), "r"(bytes) : "memory")

#define MBAR_WAIT(addr, parity) do { \
    unsigned _mb = (addr); unsigned _ph = (parity); unsigned _done; \
    asm volatile("{ .reg .pred p; mbarrier.try_wait.parity.acquire.cta.shared::cta.b64 p, [%1], %2; selp.b32 %0, 1, 0, p; }" \
                 : "=r"(_done) : "r"(_mb), "r"(_ph) : "memory"); \
    if (!_done) { \
        asm volatile("{ .reg .pred P1; WL_%=: mbarrier.try_wait.parity.acquire.cta.shared::cta.b64 P1, [%0], %1, 0x989680; @P1 bra.uni WD_%=; bra.uni WL_%=; WD_%=: }" \
                     :: "r"(_mb), "r"(_ph) : "memory"); \
    } \
} while (0)

// ---------------- k_hist (unchanged, proven) ----------------
__global__ void k_hist(const int* __restrict__ nation_idxs,
                       const int* __restrict__ piece_tile_idxs,
                       int P,
                       const float* __restrict__ tile_fc_w,
                       const float* __restrict__ tile_fc_b,
                       const float* __restrict__ piece_fc_w,
                       const float* __restrict__ piece_fc_b,
                       const float* __restrict__ tile_policy_w,
                       const float* __restrict__ tile_policy_b,
                       const float* __restrict__ nation_emb,
                       const float* __restrict__ terrain_emb,
                       const int*   __restrict__ active_nation)
{
    __shared__ float w[64];
    int tid = threadIdx.x;
    int b = blockIdx.x;

    if (b < PARAM_BLOCKS) {
        __shared__ float rA[64], rB[64], rD[64];
        if (tid < 64) w[tid] = tile_policy_w[tid];
        __syncthreads();

        if (b < 16) {
            if (tid < 64) {
                float s = 0.f;
                #pragma unroll 16
                for (int k = 0; k < 64; k++)
                    s += nation_emb[b * 64 + k] * piece_fc_w[k * 64 + tid];
                g_nproj[b * 64 + tid] = s;
            }
        } else {
            if (tid < 64) {
                float su = 0.f, sv = 0.f, t0 = 0.f, t1 = 0.f;
                #pragma unroll 16
                for (int c = 0; c < 64; c++) {
                    su += tile_fc_w[tid * 64 + c] * w[c];
                    sv += piece_fc_w[(64 + tid) * 64 + c] * w[c];
                }
                #pragma unroll 16
                for (int k = 0; k < 64; k++) {
                    float tw = tile_fc_w[(64 + k) * 64 + tid];
                    t0 += terrain_emb[k] * tw;
                    t1 += terrain_emb[64 + k] * tw;
                }
                g_u[tid] = su;
                g_v[tid] = sv;
                g_tproj[tid] = t0;
                g_tproj[64 + tid] = t1;

                int an = active_nation[0];
                rA[tid] = t0 * w[tid];
                rB[tid] = t1 * w[tid];
                rD[tid] = (tile_fc_b[tid] + nation_emb[an * 64 + tid]) * w[tid];
            }
            __syncthreads();
            if (tid < 3) {
                const float* r = (tid == 0) ? rA : (tid == 1) ? rB : rD;
                float s = 0.f;
                #pragma unroll 16
                for (int k = 0; k < 64; k++) s += r[k];
                if (tid == 0) g_terrsc[0] = s;
                else if (tid == 1) g_terrsc[1] = s;
                else g_c0 = s + tile_policy_b[0];
            }
        }
        return;
    }

    __shared__ float vtop[64], rP[64];
    __shared__ unsigned long long sq[NNAT];
    __shared__ unsigned int sh[NNAT];

    if (tid < 64) w[tid] = tile_policy_w[tid];
    __syncthreads();

    if (tid < 64) {
        const float4* pr = reinterpret_cast<const float4*>(piece_fc_w + tid * 64);
        float s = 0.f;
        #pragma unroll
        for (int c = 0; c < 16; c++) {
            float4 p = pr[c];
            s += p.x * w[4 * c] + p.y * w[4 * c + 1]
               + p.z * w[4 * c + 2] + p.w * w[4 * c + 3];
        }
        vtop[tid] = s;
    } else if (tid < 128) {
        rP[tid - 64] = piece_fc_b[tid - 64] * w[tid - 64];
    }
    __syncthreads();

    if (tid < NNAT) {
        float pb = 0.f;
        #pragma unroll 16
        for (int j = 0; j < 64; j++) pb += rP[j];
        float q = 0.f;
        #pragma unroll 16
        for (int k = 0; k < 64; k++) q += nation_emb[tid * 64 + k] * vtop[k];
        sq[tid] = (unsigned long long)llroundf((q + pb + QOFF) * QSCALE)
                + (1ULL << CNT_SHIFT);
        sh[tid] = 0u;
    }
    __syncthreads();

    int i = (b - PARAM_BLOCKS) * blockDim.x + tid;
    int Pg = P / PPT;
    if (i < Pg) {
        #pragma unroll
        for (int r = 0; r < PPT / 4; r++) {
            int4 n4 = reinterpret_cast<const int4*>(nation_idxs)[i * (PPT / 4) + r];
            int4 t4 = reinterpret_cast<const int4*>(piece_tile_idxs)[i * (PPT / 4) + r];
            atomicAdd(&g_tcu[t4.x], sq[n4.x]);
            atomicAdd(&g_tcu[t4.y], sq[n4.y]);
            atomicAdd(&g_tcu[t4.z], sq[n4.z]);
            atomicAdd(&g_tcu[t4.w], sq[n4.w]);
            atomicAdd(&sh[n4.x], 1u); atomicAdd(&sh[n4.y], 1u);
            atomicAdd(&sh[n4.z], 1u); atomicAdd(&sh[n4.w], 1u);
        }
    }
    int rem = P - Pg * PPT;
    if (i < rem) {
        int idx = Pg * PPT + i;
        atomicAdd(&g_tcu[piece_tile_idxs[idx]], sq[nation_idxs[idx]]);
        atomicAdd(&sh[nation_idxs[idx]], 1u);
    }
    __syncthreads();
    if (tid < NNAT) atomicAdd(&g_acc[128 + tid], (float)sh[tid]);
}

// ---------------- k_tiles: bulk-async staged ----------------
// 148 blocks x 512 threads. Double-buffered smem chunks of CHUNK=40 tiles
// loaded via cp.async.bulk (bypasses the per-thread MSHR wall). tp chunk is
// loaded speculatively at row==t; per-tile row check falls back to a scalar
// gather if tile_idxs is not identity. Self-cleaning tcu; fused epilogue.
__global__ void k_tiles(const int*   __restrict__ tile_idxs,
                        const int*   __restrict__ terrain,
                        const float* __restrict__ tile_pos_emb,
                        const float* __restrict__ piece_tile_emb,
                        float*       __restrict__ out,
                        int T, int P,
                        const float* __restrict__ tile_fc_w,
                        const float* __restrict__ tile_fc_b,
                        const float* __restrict__ piece_fc_w,
                        const float* __restrict__ piece_fc_b,
                        const float* __restrict__ nation_emb,
                        const int*   __restrict__ active_nation,
                        const float* __restrict__ value_w1,
                        const float* __restrict__ value_b1,
                        const float* __restrict__ value_w2,
                        const float* __restrict__ value_b2,
                        const float* __restrict__ end_turn_logit)
{
    __shared__ __align__(16) char sbuf[2 * BUFSTRIDE];
    __shared__ unsigned long long mb[2];

    int tid = threadIdx.x;
    int bid = blockIdx.x;
    int lane = tid & 31;
    int wid  = tid >> 5;                 // 0..15
    int nchunks = (T + CHUNK - 1) / CHUNK;

    unsigned mba[2];
    mba[0] = smaddr(&mb[0]);
    mba[1] = smaddr(&mb[1]);
    unsigned sb = smaddr(sbuf);

    if (tid == 0) {
        MBAR_INIT(mba[0], 1);
        MBAR_INIT(mba[1], 1);
    }
    __syncthreads();

    // Prologue: issue chunks bid (buf0) and bid+NBLK (buf1).
    if (tid == 0) {
        #pragma unroll
        for (int pb = 0; pb < 2; pb++) {
            int c = bid + pb * NBLK;
            if (c < nchunks) {
                int t0 = c * CHUNK;
                int ca = min(CHUNK, T - t0);
                unsigned off = pb * BUFSTRIDE;
                MBAR_EXPECT_TX(mba[pb], (unsigned)(ca * 528));
                BULK_G2S(sb + off + TP_OFF,  tile_pos_emb + (size_t)t0 * 64, (unsigned)(ca * 256), mba[pb]);
                BULK_G2S(sb + off + PE_OFF,  piece_tile_emb + (size_t)t0 * 64, (unsigned)(ca * 256), mba[pb]);
                BULK_G2S(sb + off + TCU_OFF, &g_tcu[t0], (unsigned)(ca * 8), mba[pb]);
                BULK_G2S(sb + off + IDX_OFF, tile_idxs + t0, (unsigned)(ca * 4), mba[pb]);
                BULK_G2S(sb + off + TER_OFF, terrain + t0, (unsigned)(ca * 4), mba[pb]);
            }
        }
    }

    float u0 = g_u[2 * lane], u1 = g_u[2 * lane + 1];
    float v0 = g_v[2 * lane], v1 = g_v[2 * lane + 1];
    float c0 = g_c0;
    float tsc0 = g_terrsc[0], tsc1 = g_terrsc[1];

    float ap0 = 0.f, ap1 = 0.f;
    float ac0 = 0.f, ac1 = 0.f;
    float tcc0 = 0.f, tcc1 = 0.f;

    const float2* __restrict__ tp_g = reinterpret_cast<const float2*>(tile_pos_emb);

    int par[2] = {0, 0};
    int k = 0;
    for (int c = bid; c < nchunks; c += NBLK, k++) {
        int b = k & 1;
        MBAR_WAIT(mba[b], (unsigned)par[b]);
        par[b] ^= 1;

        int t0 = c * CHUNK;
        int ca = min(CHUNK, T - t0);
        char* buf = sbuf + b * BUFSTRIDE;
        const float2* tp_s = reinterpret_cast<const float2*>(buf + TP_OFF);
        const float2* pe_s = reinterpret_cast<const float2*>(buf + PE_OFF);
        const unsigned long long* tcu_s = reinterpret_cast<const unsigned long long*>(buf + TCU_OFF);
        const int* idx_s = reinterpret_cast<const int*>(buf + IDX_OFF);
        const int* ter_s = reinterpret_cast<const int*>(buf + TER_OFF);
        float* res_s = reinterpret_cast<float*>(buf + RES_OFF);

        for (int tloc = wid; tloc < ca; tloc += 16) {
            int t = t0 + tloc;
            int row = idx_s[tloc];
            unsigned long long pk = tcu_s[tloc];
            float cnt = (float)(unsigned int)(pk >> CNT_SHIFT);
            float qs  = (float)(long long)(pk & ((1ULL << CNT_SHIFT) - 1ull))
                        * (1.0f / QSCALE) - cnt * QOFF;
            float2 pev = pe_s[tloc * 32 + lane];
            float2 tpv = (row == t) ? tp_s[tloc * 32 + lane]
                                    : tp_g[(size_t)row * 32 + lane];
            float s = tpv.x * u0 + tpv.y * u1 + cnt * (pev.x * v0 + pev.y * v1);
            ap0 += tpv.x; ap1 += tpv.y;
            ac0 += cnt * pev.x; ac1 += cnt * pev.y;
            #pragma unroll
            for (int o = 16; o > 0; o >>= 1)
                s += __shfl_xor_sync(0xffffffffu, s, o);
            if (lane == 0) {
                int e = ter_s[tloc] - 1;
                res_s[tloc] = s + (e == 0 ? tsc0 : tsc1) + qs + c0;
                if (e == 0) tcc0 += 1.f; else tcc1 += 1.f;
            }
        }
        __syncthreads();

        // Writeback results; restore tcu zeros for next replay.
        for (int i = tid; i < ca; i += 512) {
            out[t0 + i] = res_s[i];
            g_tcu[t0 + i] = 0ull;
        }
        __syncthreads();

        int cn = c + 2 * NBLK;
        if (tid == 0 && cn < nchunks) {
            int nt0 = cn * CHUNK;
            int nca = min(CHUNK, T - nt0);
            unsigned off = b * BUFSTRIDE;
            MBAR_EXPECT_TX(mba[b], (unsigned)(nca * 528));
            BULK_G2S(sb + off + TP_OFF,  tile_pos_emb + (size_t)nt0 * 64, (unsigned)(nca * 256), mba[b]);
            BULK_G2S(sb + off + PE_OFF,  piece_tile_emb + (size_t)nt0 * 64, (unsigned)(nca * 256), mba[b]);
            BULK_G2S(sb + off + TCU_OFF, &g_tcu[nt0], (unsigned)(nca * 8), mba[b]);
            BULK_G2S(sb + off + IDX_OFF, tile_idxs + nt0, (unsigned)(nca * 4), mba[b]);
            BULK_G2S(sb + off + TER_OFF, terrain + nt0, (unsigned)(nca * 4), mba[b]);
        }
    }

    atomicAdd(&g_acc[2 * lane],          ap0);
    atomicAdd(&g_acc[2 * lane + 1],      ap1);
    atomicAdd(&g_acc[64 + 2 * lane],     ac0);
    atomicAdd(&g_acc[64 + 2 * lane + 1], ac1);
    if (lane == 0) {
        atomicAdd(&g_acc[144], tcc0);
        atomicAdd(&g_acc[145], tcc1);
    }

    // ---- last-block epilogue ----
    __threadfence();
    __syncthreads();
    __shared__ bool isLast;
    if (tid == 0)
        isLast = (atomicAdd(&g_done, 1u) == gridDim.x - 1);
    __syncthreads();
    if (!isLast) return;

    __shared__ float part[4][64];
    __shared__ float pooled[64];
    __shared__ float h[64];
    int cc = tid >> 6;      // 0..7 (only 0..3 used)
    int j = tid & 63;
    float fT = (float)T;

    if (tid < 256) {
        float s = 0.f;
        #pragma unroll 16
        for (int kk = cc * 16; kk < cc * 16 + 16; kk++) {
            s += g_acc[kk]      * tile_fc_w[kk * 64 + j];
            s += g_acc[64 + kk] * piece_fc_w[(64 + kk) * 64 + j];
        }
        #pragma unroll 4
        for (int n = cc * 4; n < cc * 4 + 4; n++)
            s += g_acc[128 + n] * g_nproj[n * 64 + j];
        if (cc == 0) {
            s += g_acc[144] * g_tproj[j] + g_acc[145] * g_tproj[64 + j];
            int an_ = active_nation[0];
            s += fT * tile_fc_b[j] + (float)P * piece_fc_b[j]
               + fT * nation_emb[an_ * 64 + j];
        }
        part[cc][j] = s;
    }
    __syncthreads();

    if (tid < 160) g_acc[tid] = 0.f;
    if (tid == 160) g_done = 0u;
    if (tid < 64)
        pooled[j] = (part[0][j] + part[1][j] + part[2][j] + part[3][j]) / fT;
    __syncthreads();

    if (tid < 256) {
        float hv = 0.f;
        #pragma unroll 16
        for (int kk = cc * 16; kk < cc * 16 + 16; kk++)
            hv += pooled[kk] * value_w1[kk * 64 + j];
        part[cc][j] = hv;
    }
    __syncthreads();
    if (tid < 64) {
        float x = part[0][j] + part[1][j] + part[2][j] + part[3][j] + value_b1[j];
        h[j] = x > 0.f ? x : 0.f;
    }
    __syncthreads();

    if (tid < 32) {
        float v = h[tid] * value_w2[tid] + h[tid + 32] * value_w2[tid + 32];
        #pragma unroll
        for (int o = 16; o > 0; o >>= 1)
            v += __shfl_xor_sync(0xffffffffu, v, o);
        if (tid == 0) {
            out[T]     = end_turn_logit[0];
            out[T + 1] = v + value_b2[0];
        }
    }
}

extern "C" void kernel_launch(void* const* d_in, const int* in_sizes, int n_in,
                              void* d_out, int out_size)
{
    const int*   tile_idxs      = (const int*)  d_in[0];
    const int*   terrain        = (const int*)  d_in[1];
    const int*   nation_idxs    = (const int*)  d_in[2];
    const int*   piece_tidx     = (const int*)  d_in[3];
    const int*   active         = (const int*)  d_in[4];
    const float* tile_pos_emb   = (const float*)d_in[5];
    const float* terrain_emb    = (const float*)d_in[6];
    const float* nation_emb     = (const float*)d_in[7];
    const float* piece_tile_emb = (const float*)d_in[8];
    const float* tile_fc_w      = (const float*)d_in[9];
    const float* tile_fc_b      = (const float*)d_in[10];
    const float* piece_fc_w     = (const float*)d_in[11];
    const float* piece_fc_b     = (const float*)d_in[12];
    const float* tile_policy_w  = (const float*)d_in[13];
    const float* tile_policy_b  = (const float*)d_in[14];
    const float* end_turn       = (const float*)d_in[15];
    const float* value_w1       = (const float*)d_in[16];
    const float* value_b1       = (const float*)d_in[17];
    const float* value_w2       = (const float*)d_in[18];
    const float* value_b2       = (const float*)d_in[19];
    float* out = (float*)d_out;

    int T = in_sizes[0];   // 200000
    int P = in_sizes[2];   // 1000000

    int piece_blocks = (P / PPT + 255) / 256;
    k_hist<<<PARAM_BLOCKS + piece_blocks, 256>>>(
        nation_idxs, piece_tidx, P,
        tile_fc_w, tile_fc_b, piece_fc_w, piece_fc_b,
        tile_policy_w, tile_policy_b, nation_emb, terrain_emb, active);

    k_tiles<<<NBLK, 512>>>(tile_idxs, terrain, tile_pos_emb, piece_tile_emb, out,
                           T, P,
                           tile_fc_w, tile_fc_b, piece_fc_w, piece_fc_b,
                           nation_emb, active,
                           value_w1, value_b1, value_w2, value_b2, end_turn);
}

// round 17
// speedup vs baseline: 2.8527x; 1.1333x over previous
#include <cuda_runtime.h>

#define NNAT 16
#define MAX_TILES 200000

__device__ unsigned long long g_tcu[MAX_TILES];
__device__ float g_acc[160];
__device__ float g_u[64];
__device__ float g_v[64];
__device__ float g_terrsc[2];
__device__ float g_nproj[16 * 64];
__device__ float g_tproj[2 * 64];
__device__ float g_c0;
__device__ unsigned int g_done;

#define QSCALE 1073741824.0f
#define QOFF   4.0f
#define CNT_SHIFT 42
#define PARAM_BLOCKS 17
#define PPT 8

#define CHUNK 40
#define TP_OFF 0
#define PE_OFF 10240
#define TCU_OFF 20480
#define IDX_OFF 20800
#define TER_OFF 20960
#define BUFSTRIDE 21120
#define NBLK 592                 // 4 pipelines per SM

__device__ __forceinline__ unsigned smaddr(const void* p) {
    unsigned r;
    asm("{ .reg .u64 t; cvta.to.shared.u64 t, %1; cvt.u32.u64 %0, t; }"
        : "=r"(r) : "l"(p));
    return r;
}

#define BULK_G2S(dst, src, bytes, mbar) \
    asm volatile("cp.async.bulk.shared::cta.global.mbarrier::complete_tx::bytes [%0], [%1], %2, [%3];" \
                 :: "r"(dst), "l"(src), "r"(bytes), "r"(mbar) : "memory")

#define MBAR_INIT(addr, cnt) \
    asm volatile("mbarrier.init.shared.b64 [%0], %1;" :: "r"(addr), "r"(cnt) : "memory")

#define MBAR_EXPECT_TX(addr, bytes) \
    asm volatile("mbarrier.arrive.expect_tx.shared.b64 _, [%0], %1;" :: "r"(addr), "r"(bytes) : "memory")

#define MBAR_WAIT(addr, parity) do { \
    unsigned _mb = (addr); unsigned _ph = (parity); unsigned _done; \
    asm volatile("{ .reg .pred p; mbarrier.try_wait.parity.acquire.cta.shared::cta.b64 p, [%1], %2; selp.b32 %0, 1, 0, p; }" \
                 : "=r"(_done) : "r"(_mb), "r"(_ph) : "memory"); \
    if (!_done) { \
        asm volatile("{ .reg .pred P1; WL_%=: mbarrier.try_wait.parity.acquire.cta.shared::cta.b64 P1, [%0], %1, 0x989680; @P1 bra.uni WD_%=; bra.uni WL_%=; WD_%=: }" \
                     :: "r"(_mb), "r"(_ph) : "memory"); \
    } \
} while (0)

// ---------------- k_hist (unchanged, proven) ----------------
__global__ void k_hist(const int* __restrict__ nation_idxs,
                       const int* __restrict__ piece_tile_idxs,
                       int P,
                       const float* __restrict__ tile_fc_w,
                       const float* __restrict__ tile_fc_b,
                       const float* __restrict__ piece_fc_w,
                       const float* __restrict__ piece_fc_b,
                       const float* __restrict__ tile_policy_w,
                       const float* __restrict__ tile_policy_b,
                       const float* __restrict__ nation_emb,
                       const float* __restrict__ terrain_emb,
                       const int*   __restrict__ active_nation)
{
    __shared__ float w[64];
    int tid = threadIdx.x;
    int b = blockIdx.x;

    if (b < PARAM_BLOCKS) {
        __shared__ float rA[64], rB[64], rD[64];
        if (tid < 64) w[tid] = tile_policy_w[tid];
        __syncthreads();

        if (b < 16) {
            if (tid < 64) {
                float s = 0.f;
                #pragma unroll 16
                for (int k = 0; k < 64; k++)
                    s += nation_emb[b * 64 + k] * piece_fc_w[k * 64 + tid];
                g_nproj[b * 64 + tid] = s;
            }
        } else {
            if (tid < 64) {
                float su = 0.f, sv = 0.f, t0 = 0.f, t1 = 0.f;
                #pragma unroll 16
                for (int c = 0; c < 64; c++) {
                    su += tile_fc_w[tid * 64 + c] * w[c];
                    sv += piece_fc_w[(64 + tid) * 64 + c] * w[c];
                }
                #pragma unroll 16
                for (int k = 0; k < 64; k++) {
                    float tw = tile_fc_w[(64 + k) * 64 + tid];
                    t0 += terrain_emb[k] * tw;
                    t1 += terrain_emb[64 + k] * tw;
                }
                g_u[tid] = su;
                g_v[tid] = sv;
                g_tproj[tid] = t0;
                g_tproj[64 + tid] = t1;

                int an = active_nation[0];
                rA[tid] = t0 * w[tid];
                rB[tid] = t1 * w[tid];
                rD[tid] = (tile_fc_b[tid] + nation_emb[an * 64 + tid]) * w[tid];
            }
            __syncthreads();
            if (tid < 3) {
                const float* r = (tid == 0) ? rA : (tid == 1) ? rB : rD;
                float s = 0.f;
                #pragma unroll 16
                for (int k = 0; k < 64; k++) s += r[k];
                if (tid == 0) g_terrsc[0] = s;
                else if (tid == 1) g_terrsc[1] = s;
                else g_c0 = s + tile_policy_b[0];
            }
        }
        return;
    }

    __shared__ float vtop[64], rP[64];
    __shared__ unsigned long long sq[NNAT];
    __shared__ unsigned int sh[NNAT];

    if (tid < 64) w[tid] = tile_policy_w[tid];
    __syncthreads();

    if (tid < 64) {
        const float4* pr = reinterpret_cast<const float4*>(piece_fc_w + tid * 64);
        float s = 0.f;
        #pragma unroll
        for (int c = 0; c < 16; c++) {
            float4 p = pr[c];
            s += p.x * w[4 * c] + p.y * w[4 * c + 1]
               + p.z * w[4 * c + 2] + p.w * w[4 * c + 3];
        }
        vtop[tid] = s;
    } else if (tid < 128) {
        rP[tid - 64] = piece_fc_b[tid - 64] * w[tid - 64];
    }
    __syncthreads();

    if (tid < NNAT) {
        float pb = 0.f;
        #pragma unroll 16
        for (int j = 0; j < 64; j++) pb += rP[j];
        float q = 0.f;
        #pragma unroll 16
        for (int k = 0; k < 64; k++) q += nation_emb[tid * 64 + k] * vtop[k];
        sq[tid] = (unsigned long long)llroundf((q + pb + QOFF) * QSCALE)
                + (1ULL << CNT_SHIFT);
        sh[tid] = 0u;
    }
    __syncthreads();

    int i = (b - PARAM_BLOCKS) * blockDim.x + tid;
    int Pg = P / PPT;
    if (i < Pg) {
        #pragma unroll
        for (int r = 0; r < PPT / 4; r++) {
            int4 n4 = reinterpret_cast<const int4*>(nation_idxs)[i * (PPT / 4) + r];
            int4 t4 = reinterpret_cast<const int4*>(piece_tile_idxs)[i * (PPT / 4) + r];
            atomicAdd(&g_tcu[t4.x], sq[n4.x]);
            atomicAdd(&g_tcu[t4.y], sq[n4.y]);
            atomicAdd(&g_tcu[t4.z], sq[n4.z]);
            atomicAdd(&g_tcu[t4.w], sq[n4.w]);
            atomicAdd(&sh[n4.x], 1u); atomicAdd(&sh[n4.y], 1u);
            atomicAdd(&sh[n4.z], 1u); atomicAdd(&sh[n4.w], 1u);
        }
    }
    int rem = P - Pg * PPT;
    if (i < rem) {
        int idx = Pg * PPT + i;
        atomicAdd(&g_tcu[piece_tile_idxs[idx]], sq[nation_idxs[idx]]);
        atomicAdd(&sh[nation_idxs[idx]], 1u);
    }
    __syncthreads();
    if (tid < NNAT) atomicAdd(&g_acc[128 + tid], (float)sh[tid]);
}

// ---------------- k_tiles: 4 pipelines/SM bulk-async staged ----------------
// 592 blocks x 128 threads, each block a depth-2 pipeline of CHUNK=40 tiles.
// lane0 writes out[] and zeroes g_tcu inline (no staging phase); ONE
// __syncthreads per chunk. Fused last-block epilogue (128-thread version).
__global__ void k_tiles(const int*   __restrict__ tile_idxs,
                        const int*   __restrict__ terrain,
                        const float* __restrict__ tile_pos_emb,
                        const float* __restrict__ piece_tile_emb,
                        float*       __restrict__ out,
                        int T, int P,
                        const float* __restrict__ tile_fc_w,
                        const float* __restrict__ tile_fc_b,
                        const float* __restrict__ piece_fc_w,
                        const float* __restrict__ piece_fc_b,
                        const float* __restrict__ nation_emb,
                        const int*   __restrict__ active_nation,
                        const float* __restrict__ value_w1,
                        const float* __restrict__ value_b1,
                        const float* __restrict__ value_w2,
                        const float* __restrict__ value_b2,
                        const float* __restrict__ end_turn_logit)
{
    __shared__ __align__(16) char sbuf[2 * BUFSTRIDE];
    __shared__ unsigned long long mb[2];

    int tid = threadIdx.x;
    int bid = blockIdx.x;
    int lane = tid & 31;
    int wid  = tid >> 5;                 // 0..3
    int nchunks = (T + CHUNK - 1) / CHUNK;

    unsigned mba[2];
    mba[0] = smaddr(&mb[0]);
    mba[1] = smaddr(&mb[1]);
    unsigned sb = smaddr(sbuf);

    if (tid == 0) {
        MBAR_INIT(mba[0], 1);
        MBAR_INIT(mba[1], 1);
    }
    __syncthreads();

    if (tid == 0) {
        #pragma unroll
        for (int pb = 0; pb < 2; pb++) {
            int c = bid + pb * NBLK;
            if (c < nchunks) {
                int t0 = c * CHUNK;
                int ca = min(CHUNK, T - t0);
                unsigned off = pb * BUFSTRIDE;
                MBAR_EXPECT_TX(mba[pb], (unsigned)(ca * 528));
                BULK_G2S(sb + off + TP_OFF,  tile_pos_emb + (size_t)t0 * 64, (unsigned)(ca * 256), mba[pb]);
                BULK_G2S(sb + off + PE_OFF,  piece_tile_emb + (size_t)t0 * 64, (unsigned)(ca * 256), mba[pb]);
                BULK_G2S(sb + off + TCU_OFF, &g_tcu[t0], (unsigned)(ca * 8), mba[pb]);
                BULK_G2S(sb + off + IDX_OFF, tile_idxs + t0, (unsigned)(ca * 4), mba[pb]);
                BULK_G2S(sb + off + TER_OFF, terrain + t0, (unsigned)(ca * 4), mba[pb]);
            }
        }
    }

    float u0 = g_u[2 * lane], u1 = g_u[2 * lane + 1];
    float v0 = g_v[2 * lane], v1 = g_v[2 * lane + 1];
    float c0 = g_c0;
    float tsc0 = g_terrsc[0], tsc1 = g_terrsc[1];

    float ap0 = 0.f, ap1 = 0.f;
    float ac0 = 0.f, ac1 = 0.f;
    float tcc0 = 0.f, tcc1 = 0.f;

    const float2* __restrict__ tp_g = reinterpret_cast<const float2*>(tile_pos_emb);

    int par[2] = {0, 0};
    int k = 0;
    for (int c = bid; c < nchunks; c += NBLK, k++) {
        int b = k & 1;
        MBAR_WAIT(mba[b], (unsigned)par[b]);
        par[b] ^= 1;

        int t0 = c * CHUNK;
        int ca = min(CHUNK, T - t0);
        char* buf = sbuf + b * BUFSTRIDE;
        const float2* tp_s = reinterpret_cast<const float2*>(buf + TP_OFF);
        const float2* pe_s = reinterpret_cast<const float2*>(buf + PE_OFF);
        const unsigned long long* tcu_s = reinterpret_cast<const unsigned long long*>(buf + TCU_OFF);
        const int* idx_s = reinterpret_cast<const int*>(buf + IDX_OFF);
        const int* ter_s = reinterpret_cast<const int*>(buf + TER_OFF);

        for (int tloc = wid; tloc < ca; tloc += 4) {
            int t = t0 + tloc;
            int row = idx_s[tloc];
            unsigned long long pk = tcu_s[tloc];
            float cnt = (float)(unsigned int)(pk >> CNT_SHIFT);
            float qs  = (float)(long long)(pk & ((1ULL << CNT_SHIFT) - 1ull))
                        * (1.0f / QSCALE) - cnt * QOFF;
            float2 pev = pe_s[tloc * 32 + lane];
            float2 tpv = (row == t) ? tp_s[tloc * 32 + lane]
                                    : tp_g[(size_t)row * 32 + lane];
            float s = tpv.x * u0 + tpv.y * u1 + cnt * (pev.x * v0 + pev.y * v1);
            ap0 += tpv.x; ap1 += tpv.y;
            ac0 += cnt * pev.x; ac1 += cnt * pev.y;
            #pragma unroll
            for (int o = 16; o > 0; o >>= 1)
                s += __shfl_xor_sync(0xffffffffu, s, o);
            if (lane == 0) {
                int e = ter_s[tloc] - 1;
                out[t] = s + (e == 0 ? tsc0 : tsc1) + qs + c0;
                g_tcu[t] = 0ull;                     // restore zero for next replay
                if (e == 0) tcc0 += 1.f; else tcc1 += 1.f;
            }
        }
        __syncthreads();                             // all warps done reading buffer b

        int cn = c + 2 * NBLK;
        if (tid == 0 && cn < nchunks) {
            int nt0 = cn * CHUNK;
            int nca = min(CHUNK, T - nt0);
            unsigned off = b * BUFSTRIDE;
            MBAR_EXPECT_TX(mba[b], (unsigned)(nca * 528));
            BULK_G2S(sb + off + TP_OFF,  tile_pos_emb + (size_t)nt0 * 64, (unsigned)(nca * 256), mba[b]);
            BULK_G2S(sb + off + PE_OFF,  piece_tile_emb + (size_t)nt0 * 64, (unsigned)(nca * 256), mba[b]);
            BULK_G2S(sb + off + TCU_OFF, &g_tcu[nt0], (unsigned)(nca * 8), mba[b]);
            BULK_G2S(sb + off + IDX_OFF, tile_idxs + nt0, (unsigned)(nca * 4), mba[b]);
            BULK_G2S(sb + off + TER_OFF, terrain + nt0, (unsigned)(nca * 4), mba[b]);
        }
    }

    atomicAdd(&g_acc[2 * lane],          ap0);
    atomicAdd(&g_acc[2 * lane + 1],      ap1);
    atomicAdd(&g_acc[64 + 2 * lane],     ac0);
    atomicAdd(&g_acc[64 + 2 * lane + 1], ac1);
    if (lane == 0) {
        atomicAdd(&g_acc[144], tcc0);
        atomicAdd(&g_acc[145], tcc1);
    }

    // ---- last-block epilogue (128 threads) ----
    __threadfence();
    __syncthreads();
    __shared__ bool isLast;
    if (tid == 0)
        isLast = (atomicAdd(&g_done, 1u) == gridDim.x - 1);
    __syncthreads();
    if (!isLast) return;

    __shared__ float part[2][64];
    __shared__ float pooled[64];
    __shared__ float h[64];
    int cc = tid >> 6;      // 0..1
    int j = tid & 63;
    float fT = (float)T;

    float s = 0.f;
    #pragma unroll 8
    for (int kk = cc * 32; kk < cc * 32 + 32; kk++) {
        s += g_acc[kk]      * tile_fc_w[kk * 64 + j];
        s += g_acc[64 + kk] * piece_fc_w[(64 + kk) * 64 + j];
    }
    #pragma unroll 8
    for (int n = cc * 8; n < cc * 8 + 8; n++)
        s += g_acc[128 + n] * g_nproj[n * 64 + j];
    if (cc == 0) {
        s += g_acc[144] * g_tproj[j] + g_acc[145] * g_tproj[64 + j];
        int an_ = active_nation[0];
        s += fT * tile_fc_b[j] + (float)P * piece_fc_b[j]
           + fT * nation_emb[an_ * 64 + j];
    }
    part[cc][j] = s;
    __syncthreads();

    // Restore zeros for next replay.
    g_acc[tid] = 0.f;                  // 0..127
    if (tid < 32) g_acc[128 + tid] = 0.f;
    if (tid == 0) g_done = 0u;

    if (tid < 64)
        pooled[j] = (part[0][j] + part[1][j]) / fT;
    __syncthreads();

    float hv = 0.f;
    #pragma unroll 8
    for (int kk = cc * 32; kk < cc * 32 + 32; kk++)
        hv += pooled[kk] * value_w1[kk * 64 + j];
    part[cc][j] = hv;
    __syncthreads();
    if (tid < 64) {
        float x = part[0][j] + part[1][j] + value_b1[j];
        h[j] = x > 0.f ? x : 0.f;
    }
    __syncthreads();

    if (tid < 32) {
        float v = h[tid] * value_w2[tid] + h[tid + 32] * value_w2[tid + 32];
        #pragma unroll
        for (int o = 16; o > 0; o >>= 1)
            v += __shfl_xor_sync(0xffffffffu, v, o);
        if (tid == 0) {
            out[T]     = end_turn_logit[0];
            out[T + 1] = v + value_b2[0];
        }
    }
}

extern "C" void kernel_launch(void* const* d_in, const int* in_sizes, int n_in,
                              void* d_out, int out_size)
{
    const int*   tile_idxs      = (const int*)  d_in[0];
    const int*   terrain        = (const int*)  d_in[1];
    const int*   nation_idxs    = (const int*)  d_in[2];
    const int*   piece_tidx     = (const int*)  d_in[3];
    const int*   active         = (const int*)  d_in[4];
    const float* tile_pos_emb   = (const float*)d_in[5];
    const float* terrain_emb    = (const float*)d_in[6];
    const float* nation_emb     = (const float*)d_in[7];
    const float* piece_tile_emb = (const float*)d_in[8];
    const float* tile_fc_w      = (const float*)d_in[9];
    const float* tile_fc_b      = (const float*)d_in[10];
    const float* piece_fc_w     = (const float*)d_in[11];
    const float* piece_fc_b     = (const float*)d_in[12];
    const float* tile_policy_w  = (const float*)d_in[13];
    const float* tile_policy_b  = (const float*)d_in[14];
    const float* end_turn       = (const float*)d_in[15];
    const float* value_w1       = (const float*)d_in[16];
    const float* value_b1       = (const float*)d_in[17];
    const float* value_w2       = (const float*)d_in[18];
    const float* value_b2       = (const float*)d_in[19];
    float* out = (float*)d_out;

    int T = in_sizes[0];   // 200000
    int P = in_sizes[2];   // 1000000

    int piece_blocks = (P / PPT + 255) / 256;
    k_hist<<<PARAM_BLOCKS + piece_blocks, 256>>>(
        nation_idxs, piece_tidx, P,
        tile_fc_w, tile_fc_b, piece_fc_w, piece_fc_b,
        tile_policy_w, tile_policy_b, nation_emb, terrain_emb, active);

    k_tiles<<<NBLK, 128>>>(tile_idxs, terrain, tile_pos_emb, piece_tile_emb, out,
                           T, P,
                           tile_fc_w, tile_fc_b, piece_fc_w, piece_fc_b,
                           nation_emb, active,
                           value_w1, value_b1, value_w2, value_b2, end_turn);
}